// round 7
// baseline (speedup 1.0000x reference)
#include <cuda_runtime.h>
#include <math.h>
#include <stdint.h>

// Problem constants
#define NA   8      // agents
#define NDm  16     // N_DUMMY (timesteps)
#define Bb_  1024   // batch
#define Pp_  128    // plan
#define TP   256    // 2*P
#define Hh   256    // hidden
#define H3   768    // 3*H
#define H2   512    // 2*H
#define NC   16     // chains = agents * 2 dirs
#define ROWS 16384  // NDm * Bb_

// ---------------- scratch (device globals; no allocation allowed) -------------
__device__ float g_xg[NC * ROWS * TP];        // gathered inputs per chain
__device__ float g_gi[(long)NC * ROWS * H3];  // input projections (interleaved)
__device__ float g_outf[NA * ROWS * Hh];      // forward GRU outputs
__device__ float g_outb[NA * ROWS * Hh];      // backward GRU outputs
__device__ float g_scln[NA * ROWS * H2];      // scattered + layernormed
__device__ float g_h1[NA * ROWS * Hh];        // MLP hidden
__device__ float g_h[NC * Bb_ * Hh];          // GRU hidden state (fp32)
__device__ float g_hr0[NC * Bb_ * Hh];        // tf32-rounded h, parity 0
__device__ float g_hr1[NC * Bb_ * Hh];        // tf32-rounded h, parity 1
__device__ float g_wht[NC * H3 * Hh];         // pre-rounded interleaved Wh
__device__ int   g_fwd[ROWS], g_bwd[ROWS], g_scat[ROWS];
__device__ int   g_Pmask[ROWS], g_Ppm[ROWS];
__device__ int   g_seq[Bb_], g_empty[Bb_];
__device__ int   g_anyc[Bb_ * NA], g_anyp[Bb_ * NA];
__device__ unsigned char g_mreal[NA * Bb_];

__device__ __forceinline__ uint32_t f2tf32(float f) {
    uint32_t u;
    asm("cvt.rna.tf32.f32 %0, %1;" : "=r"(u) : "f"(f));
    return u;
}

// ---------------- K1: per-(b,n) nonzero row flags ----------------------------
__global__ void __launch_bounds__(256) k_rowflags(
    const float* __restrict__ comm_plans,
    const float* __restrict__ plans,
    int* __restrict__ anyc, int* __restrict__ anyp)
{
    int warp = (blockIdx.x * blockDim.x + threadIdx.x) >> 5;
    int lane = threadIdx.x & 31;
    if (warp >= Bb_ * NA) return;
    float4 c4 = *reinterpret_cast<const float4*>(&comm_plans[(long)warp * Pp_ + lane * 4]);
    bool nzc = (c4.x != 0.f) || (c4.y != 0.f) || (c4.z != 0.f) || (c4.w != 0.f);
    unsigned mc = __ballot_sync(0xffffffffu, nzc);
    float4 p4 = *reinterpret_cast<const float4*>(&plans[(long)warp * Pp_ + lane * 4]);
    bool nzp = (p4.x != 0.f) || (p4.y != 0.f) || (p4.z != 0.f) || (p4.w != 0.f);
    unsigned mp = __ballot_sync(0xffffffffu, nzp);
    if (lane == 0) { anyc[warp] = (mc != 0u); anyp[warp] = (mp != 0u); }
}

// ---------------- K2: empty[b], mask_real[n][b] ------------------------------
__global__ void __launch_bounds__(256) k_maskreal(
    const int* __restrict__ anyc, const int* __restrict__ anyp,
    int* __restrict__ empty, unsigned char* __restrict__ mreal)
{
    int b = blockIdx.x * blockDim.x + threadIdx.x;
    if (b >= Bb_) return;
    int any = 0, ac[NA];
    #pragma unroll
    for (int n = 0; n < NA; n++) { ac[n] = anyc[b * NA + n]; any |= ac[n]; }
    int e = !any;
    empty[b] = e;
    #pragma unroll
    for (int n = 0; n < NA; n++)
        mreal[n * Bb_ + b] = e ? (unsigned char)anyp[b * NA + n] : (unsigned char)ac[n];
}

// ---------------- K3: packing index maps (single block) ----------------------
__global__ void __launch_bounds__(1024) k_indices(
    const unsigned char* __restrict__ mreal,
    int* __restrict__ seq_len,
    int* __restrict__ fwd_src, int* __restrict__ bwd_src,
    int* __restrict__ scat_src,
    int* __restrict__ Pmask, int* __restrict__ Ppm)
{
    int tid = threadIdx.x;            // 1024 threads
    {
        int b = tid, s = NDm - NA;
        #pragma unroll
        for (int t = 0; t < NA; t++) s += mreal[t * Bb_ + b];
        seq_len[b] = s;
    }
    __syncthreads();

    int base_j = tid * 16;
    unsigned m_bits = 0, p_bits = 0;
    int cm = 0, cp = 0;
    for (int r = 0; r < 16; r++) {
        int j = base_j + r;
        int t = j >> 10, b = j & 1023;
        int m = (t < NA) ? (int)mreal[j] : 1;
        int p = (t < seq_len[b]) ? 1 : 0;
        if (m) { m_bits |= 1u << r; cm++; }
        if (p) { p_bits |= 1u << r; cp++; }
    }
    __shared__ int wm[32], wp[32], tot;
    int lane = tid & 31, wid = tid >> 5;
    int sm = cm, sp = cp;
    #pragma unroll
    for (int o = 1; o < 32; o <<= 1) {
        int v = __shfl_up_sync(0xffffffffu, sm, o); if (lane >= o) sm += v;
        v     = __shfl_up_sync(0xffffffffu, sp, o); if (lane >= o) sp += v;
    }
    if (lane == 31) { wm[wid] = sm; wp[wid] = sp; }
    __syncthreads();
    if (wid == 0) {
        int a = wm[lane], c = wp[lane];
        #pragma unroll
        for (int o = 1; o < 32; o <<= 1) {
            int v = __shfl_up_sync(0xffffffffu, a, o); if (lane >= o) a += v;
            v     = __shfl_up_sync(0xffffffffu, c, o); if (lane >= o) c += v;
        }
        wm[lane] = a; wp[lane] = c;
        if (lane == 31) tot = a;
    }
    __syncthreads();
    int basem = sm - cm + (wid ? wm[wid - 1] : 0);
    int basep = sp - cp + (wid ? wp[wid - 1] : 0);
    int Ktot = tot;

    int km = basem, kp = basep;
    for (int r = 0; r < 16; r++) {
        int j = base_j + r;
        fwd_src[j] = -1;
        if (m_bits & (1u << r)) { Pmask[km] = j; scat_src[j] = km; km++; }
        else scat_src[j] = -1;
        if (p_bits & (1u << r)) { Ppm[kp] = j; kp++; }
    }
    __syncthreads();
    for (int k = tid; k < Ktot; k += 1024) fwd_src[Ppm[k]] = Pmask[k];
    __syncthreads();
    for (int r = 0; r < 16; r++) {
        int j = base_j + r;
        int t = j >> 10, b = j & 1023;
        int sl = seq_len[b];
        bwd_src[j] = (t < sl) ? fwd_src[(sl - 1 - t) * Bb_ + b] : -1;
    }
}

// ---------------- K4: init h (fp32 + tf32-rounded copy) ----------------------
__global__ void __launch_bounds__(256) k_prep_h0(
    const float* __restrict__ src, float* __restrict__ h, float* __restrict__ hr, int n)
{
    int i = blockIdx.x * blockDim.x + threadIdx.x;
    if (i < n) {
        float v = src[i];
        h[i] = v;
        hr[i] = __uint_as_float(f2tf32(v));
    }
}

// ---------------- K4b: pre-round + interleave Wh -----------------------------
__global__ void __launch_bounds__(256) k_prep_wh(
    const float* __restrict__ Wh_f, const float* __restrict__ Wh_b,
    float* __restrict__ wht)
{
    long idx = (long)blockIdx.x * 256 + threadIdx.x;
    if (idx >= (long)NC * H3 * Hh) return;
    int k = (int)(idx % Hh);
    long r2 = idx / Hh;
    int n = (int)(r2 % H3);
    int z = (int)(r2 / H3);
    int i = z >> 1, d = z & 1;
    int orig = (n % 3) * Hh + n / 3;     // interleave: n = hc*3+gate -> gate*H + hc
    const float* src = d ? Wh_b : Wh_f;
    float v = src[((long)i * H3 + orig) * Hh + k];
    wht[idx] = __uint_as_float(f2tf32(v));
}

// ---------------- K5: gather x rows per chain --------------------------------
__global__ void __launch_bounds__(64) k_gather(
    const float* __restrict__ plans, const float* __restrict__ comm_plans,
    const float* __restrict__ dummy,
    const int* __restrict__ fwd_src, const int* __restrict__ bwd_src,
    const int* __restrict__ empty, float* __restrict__ xg)
{
    int j = blockIdx.x;           // 0..16383 packed row (t*B+b)
    int z = blockIdx.y;           // chain
    int c = threadIdx.x * 4;      // 64 threads * 4 = 256 feats
    int i = z >> 1, d = z & 1;
    int src = (d ? bwd_src : fwd_src)[j];
    float4 v = make_float4(0.f, 0.f, 0.f, 0.f);
    if (src >= 0) {
        int ts = src >> 10, bs = src & 1023;
        if (ts < NA) {
            if (c < Pp_) {
                v = *reinterpret_cast<const float4*>(&plans[((long)bs * NA + i) * Pp_ + c]);
            } else {
                const float* sp = empty[bs] ? plans : comm_plans;
                v = *reinterpret_cast<const float4*>(&sp[((long)bs * NA + ts) * Pp_ + (c - Pp_)]);
            }
        } else {
            v = *reinterpret_cast<const float4*>(
                &dummy[(((long)i * (NDm - NA) + (ts - NA)) * Bb_ + bs) * TP + c]);
        }
    }
    *reinterpret_cast<float4*>(&xg[((long)z * ROWS + j) * TP + c]) = v;
}

// ---------------- tf32 tensor-core NT GEMM (input proj + MLP) ----------------
#define BM 128
#define BN 128
#define BKq 16
#define SSTR 20

__global__ void __launch_bounds__(256, 2) gemm_tf32(
    const float* __restrict__ Abase, const float* __restrict__ Bf,
    const float* __restrict__ Bbm, float* __restrict__ Cbase,
    const float* __restrict__ biasBase,
    int M, int N, int K,
    long sA, long sB, long sC, long sBias,
    int paired, int relu, int ilv)
{
    int z = blockIdx.z;
    const float* A = Abase + (long)z * sA;
    const float* W;
    if (paired) { int i = z >> 1, d = z & 1; W = (d ? Bbm : Bf) + (long)i * sB; }
    else        { W = Bf + (long)z * sB; }
    float* C = Cbase + (long)z * sC;
    const float* bias = biasBase ? (biasBase + (long)z * sBias) : nullptr;

    __shared__ __align__(16) uint32_t Ash[BM * SSTR];
    __shared__ __align__(16) uint32_t Bsh[BN * SSTR];

    int tid  = threadIdx.x;
    int lane = tid & 31;
    int warp = tid >> 5;
    int wm   = warp & 3;
    int wn   = warp >> 2;
    int m0   = blockIdx.x * BM;
    int n0   = blockIdx.y * BN;

    float acc[2][8][4];
    #pragma unroll
    for (int a = 0; a < 2; a++)
        #pragma unroll
        for (int b = 0; b < 8; b++)
            #pragma unroll
            for (int c = 0; c < 4; c++) acc[a][b][c] = 0.f;

    for (int k0 = 0; k0 < K; k0 += BKq) {
        if (k0) __syncthreads();
        #pragma unroll
        for (int i = 0; i < 2; i++) {
            int c   = tid + i * 256;
            int row = c >> 2;
            int kq  = (c & 3) * 4;
            float4 va = *reinterpret_cast<const float4*>(&A[(long)(m0 + row) * K + k0 + kq]);
            uint4 ua;
            ua.x = f2tf32(va.x); ua.y = f2tf32(va.y); ua.z = f2tf32(va.z); ua.w = f2tf32(va.w);
            *reinterpret_cast<uint4*>(&Ash[row * SSTR + kq]) = ua;
            int nn = n0 + row;
            int wrow = ilv ? ((nn % 3) * Hh + nn / 3) : nn;
            float4 vb = *reinterpret_cast<const float4*>(&W[(long)wrow * K + k0 + kq]);
            uint4 ub;
            ub.x = f2tf32(vb.x); ub.y = f2tf32(vb.y); ub.z = f2tf32(vb.z); ub.w = f2tf32(vb.w);
            *reinterpret_cast<uint4*>(&Bsh[row * SSTR + kq]) = ub;
        }
        __syncthreads();

        #pragma unroll
        for (int ks = 0; ks < BKq; ks += 8) {
            uint32_t afr[2][4], bfr[8][2];
            int ar = wm * 32 + (lane >> 2);
            int ac = ks + (lane & 3);
            #pragma unroll
            for (int mt = 0; mt < 2; mt++) {
                int r = ar + mt * 16;
                afr[mt][0] = Ash[r * SSTR + ac];
                afr[mt][1] = Ash[(r + 8) * SSTR + ac];
                afr[mt][2] = Ash[r * SSTR + ac + 4];
                afr[mt][3] = Ash[(r + 8) * SSTR + ac + 4];
            }
            int bn = wn * 64 + (lane >> 2);
            int bk = ks + (lane & 3);
            #pragma unroll
            for (int nt = 0; nt < 8; nt++) {
                int n = bn + nt * 8;
                bfr[nt][0] = Bsh[n * SSTR + bk];
                bfr[nt][1] = Bsh[n * SSTR + bk + 4];
            }
            #pragma unroll
            for (int mt = 0; mt < 2; mt++)
                #pragma unroll
                for (int nt = 0; nt < 8; nt++)
                    asm volatile(
                        "mma.sync.aligned.m16n8k8.row.col.f32.tf32.tf32.f32 "
                        "{%0,%1,%2,%3}, {%4,%5,%6,%7}, {%8,%9}, {%0,%1,%2,%3};"
                        : "+f"(acc[mt][nt][0]), "+f"(acc[mt][nt][1]),
                          "+f"(acc[mt][nt][2]), "+f"(acc[mt][nt][3])
                        : "r"(afr[mt][0]), "r"(afr[mt][1]), "r"(afr[mt][2]), "r"(afr[mt][3]),
                          "r"(bfr[nt][0]), "r"(bfr[nt][1]));
        }
    }

    #pragma unroll
    for (int mt = 0; mt < 2; mt++) {
        int r0 = m0 + wm * 32 + mt * 16 + (lane >> 2);
        #pragma unroll
        for (int nt = 0; nt < 8; nt++) {
            int cb = n0 + wn * 64 + nt * 8 + (lane & 3) * 2;
            float v0 = acc[mt][nt][0], v1 = acc[mt][nt][1];
            float v2 = acc[mt][nt][2], v3 = acc[mt][nt][3];
            if (bias) {
                float b0v = bias[cb], b1v = bias[cb + 1];
                v0 += b0v; v1 += b1v; v2 += b0v; v3 += b1v;
            }
            if (relu) {
                v0 = fmaxf(v0, 0.f); v1 = fmaxf(v1, 0.f);
                v2 = fmaxf(v2, 0.f); v3 = fmaxf(v3, 0.f);
            }
            *reinterpret_cast<float2*>(&C[(long)r0 * N + cb])       = make_float2(v0, v1);
            *reinterpret_cast<float2*>(&C[(long)(r0 + 8) * N + cb]) = make_float2(v2, v3);
        }
    }
}

// ---------------- fused recurrence step: gh GEMM + gates ---------------------
// BM=128 batch rows, BN=192 cols (=64 complete gate triples), K=256.
// A = tf32-rounded h (read buffer), B = pre-rounded interleaved Wh.
// Epilogue: acc -> smem -> gate math -> h (fp32), hr (tf32, write buffer), out.
#define RBM 128
#define RBN 192
#define RBK 16
#define RSTR 20
#define STAGE_W ((RBM + RBN) * RSTR)   // 6400 words per stage
#define EPISTR 200

__device__ __forceinline__ void cpa16(uint32_t dst, const float* src) {
    asm volatile("cp.async.ca.shared.global [%0], [%1], 16;" :: "r"(dst), "l"(src));
}

__global__ void __launch_bounds__(256, 1) k_rec_fused(
    const float* __restrict__ hr_in,   // [NC][1024][256] tf32-rounded
    float* __restrict__ h,             // [NC][1024][256] fp32
    float* __restrict__ hr_out,        // [NC][1024][256] tf32-rounded (next)
    const float* __restrict__ wht,     // [NC][768][256] interleaved, pre-rounded
    const float* __restrict__ gi,      // [NC][ROWS][768] interleaved
    float* __restrict__ outf, float* __restrict__ outb,
    const int* __restrict__ seq_len, int t)
{
    extern __shared__ float dynsm[];
    int z  = blockIdx.z;
    int m0 = blockIdx.x * RBM;
    int n0 = blockIdx.y * RBN;
    int hc0 = n0 / 3;

    const float* A = hr_in + (long)z * Bb_ * Hh;
    const float* W = wht + (long)z * H3 * Hh;

    int tid  = threadIdx.x;
    int lane = tid & 31;
    int warp = tid >> 5;
    int wm   = warp & 3;     // 4 row-warps of 32
    int wn   = warp >> 2;    // 2 col-warps of 96

    uint32_t smem_base;
    {
        void* p = dynsm;
        smem_base = (uint32_t)__cvta_generic_to_shared(p);
    }

    float acc[2][12][4];
    #pragma unroll
    for (int a = 0; a < 2; a++)
        #pragma unroll
        for (int b = 0; b < 12; b++)
            #pragma unroll
            for (int c = 0; c < 4; c++) acc[a][b][c] = 0.f;

    // ---- stage loader (cp.async) ----
    auto load_stage = [&](int buf, int k0) {
        uint32_t sA = smem_base + (buf * STAGE_W) * 4;
        uint32_t sB = smem_base + (buf * STAGE_W + RBM * RSTR) * 4;
        #pragma unroll
        for (int i = 0; i < 2; i++) {
            int cc = tid + i * 256;           // 0..511
            int row = cc >> 2, kq = (cc & 3) * 4;
            cpa16(sA + (row * RSTR + kq) * 4, &A[(long)(m0 + row) * Hh + k0 + kq]);
        }
        #pragma unroll
        for (int i = 0; i < 3; i++) {
            int cc = tid + i * 256;           // 0..767
            int row = cc >> 2, kq = (cc & 3) * 4;
            cpa16(sB + (row * RSTR + kq) * 4, &W[(long)(n0 + row) * Hh + k0 + kq]);
        }
    };

    load_stage(0, 0);
    asm volatile("cp.async.commit_group;");

    const int NSTG = Hh / RBK;   // 16
    for (int s = 0; s < NSTG; s++) {
        int buf = s & 1;
        if (s + 1 < NSTG) {
            load_stage((s + 1) & 1, (s + 1) * RBK);
            asm volatile("cp.async.commit_group;");
            asm volatile("cp.async.wait_group 1;");
        } else {
            asm volatile("cp.async.wait_group 0;");
        }
        __syncthreads();

        const uint32_t* Ash = reinterpret_cast<const uint32_t*>(dynsm + buf * STAGE_W);
        const uint32_t* Bsh = reinterpret_cast<const uint32_t*>(dynsm + buf * STAGE_W + RBM * RSTR);

        #pragma unroll
        for (int ks = 0; ks < RBK; ks += 8) {
            uint32_t afr[2][4], bfr[12][2];
            int ar = wm * 32 + (lane >> 2);
            int ac = ks + (lane & 3);
            #pragma unroll
            for (int mt = 0; mt < 2; mt++) {
                int r = ar + mt * 16;
                afr[mt][0] = Ash[r * RSTR + ac];
                afr[mt][1] = Ash[(r + 8) * RSTR + ac];
                afr[mt][2] = Ash[r * RSTR + ac + 4];
                afr[mt][3] = Ash[(r + 8) * RSTR + ac + 4];
            }
            int bn = wn * 96 + (lane >> 2);
            int bk = ks + (lane & 3);
            #pragma unroll
            for (int nt = 0; nt < 12; nt++) {
                int n = bn + nt * 8;
                bfr[nt][0] = Bsh[n * RSTR + bk];
                bfr[nt][1] = Bsh[n * RSTR + bk + 4];
            }
            #pragma unroll
            for (int mt = 0; mt < 2; mt++)
                #pragma unroll
                for (int nt = 0; nt < 12; nt++)
                    asm volatile(
                        "mma.sync.aligned.m16n8k8.row.col.f32.tf32.tf32.f32 "
                        "{%0,%1,%2,%3}, {%4,%5,%6,%7}, {%8,%9}, {%0,%1,%2,%3};"
                        : "+f"(acc[mt][nt][0]), "+f"(acc[mt][nt][1]),
                          "+f"(acc[mt][nt][2]), "+f"(acc[mt][nt][3])
                        : "r"(afr[mt][0]), "r"(afr[mt][1]), "r"(afr[mt][2]), "r"(afr[mt][3]),
                          "r"(bfr[nt][0]), "r"(bfr[nt][1]));
        }
        __syncthreads();
    }

    // ---- stash gh tile to smem ----
    #pragma unroll
    for (int mt = 0; mt < 2; mt++) {
        int rr = wm * 32 + mt * 16 + (lane >> 2);
        #pragma unroll
        for (int nt = 0; nt < 12; nt++) {
            int cb = wn * 96 + nt * 8 + (lane & 3) * 2;
            dynsm[rr * EPISTR + cb]           = acc[mt][nt][0];
            dynsm[rr * EPISTR + cb + 1]       = acc[mt][nt][1];
            dynsm[(rr + 8) * EPISTR + cb]     = acc[mt][nt][2];
            dynsm[(rr + 8) * EPISTR + cb + 1] = acc[mt][nt][3];
        }
    }
    __syncthreads();

    // ---- gate math: 128 rows x 64 hidden cols ----
    int ii = z >> 1, d = z & 1;
    float* outp = (d == 0 ? outf : outb);
    for (int idx = tid; idx < RBM * 64; idx += 256) {
        int row = idx >> 6;
        int hc  = idx & 63;
        int b   = m0 + row;
        long gbase = (((long)z * ROWS + (long)t * Bb_ + b) * H3) + (long)(hc0 + hc) * 3;
        float gir = gi[gbase], giz = gi[gbase + 1], gin = gi[gbase + 2];
        float ghr = dynsm[row * EPISTR + hc * 3];
        float ghz = dynsm[row * EPISTR + hc * 3 + 1];
        float ghn = dynsm[row * EPISTR + hc * 3 + 2];
        long ho = ((long)z * Bb_ + b) * Hh + (hc0 + hc);
        float hp = h[ho];
        float r  = 1.f / (1.f + expf(-(gir + ghr)));
        float zz = 1.f / (1.f + expf(-(giz + ghz)));
        float nn = tanhf(gin + r * ghn);
        float hn = (1.f - zz) * nn + zz * hp;
        bool v = t < seq_len[b];
        float hnew = v ? hn : hp;
        h[ho] = hnew;
        hr_out[ho] = __uint_as_float(f2tf32(hnew));
        outp[((long)ii * ROWS + (long)t * Bb_ + b) * Hh + (hc0 + hc)] = v ? hn : 0.f;
    }
}

// ---------------- K7: scatter + reverse + layernorm --------------------------
__global__ void __launch_bounds__(128) k_scores_ln(
    const float* __restrict__ outf, const float* __restrict__ outb,
    const int* __restrict__ scat, const int* __restrict__ seq_len,
    const float* __restrict__ ln_g, const float* __restrict__ ln_b,
    float* __restrict__ scln)
{
    int j = blockIdx.x;          // row (t*B+b) in mask layout
    int i = blockIdx.y;          // agent
    int tid = threadIdx.x;       // 128 threads, 4 cols each
    __shared__ float s1[128], s2[128];
    float v0 = 0.f, v1 = 0.f, v2 = 0.f, v3 = 0.f;
    int k = scat[j];
    if (k >= 0) {
        int tp = k >> 10, bp = k & 1023;
        if (tid < 64) {
            float4 f = *reinterpret_cast<const float4*>(&outf[((long)i * ROWS + k) * Hh + tid * 4]);
            v0 = f.x; v1 = f.y; v2 = f.z; v3 = f.w;
        } else {
            int sl = seq_len[bp];
            if (tp < sl) {
                int rb = sl - 1 - tp;
                float4 f = *reinterpret_cast<const float4*>(
                    &outb[((long)i * ROWS + rb * Bb_ + bp) * Hh + (tid - 64) * 4]);
                v0 = f.x; v1 = f.y; v2 = f.z; v3 = f.w;
            }
        }
    }
    s1[tid] = v0 + v1 + v2 + v3;
    s2[tid] = v0 * v0 + v1 * v1 + v2 * v2 + v3 * v3;
    __syncthreads();
    for (int off = 64; off > 0; off >>= 1) {
        if (tid < off) { s1[tid] += s1[tid + off]; s2[tid] += s2[tid + off]; }
        __syncthreads();
    }
    float mu  = s1[0] * (1.f / H2);
    float var = s2[0] * (1.f / H2) - mu * mu;
    float rs  = rsqrtf(var + 1e-5f);
    int c = tid * 4;
    const float* g = &ln_g[i * H2 + c];
    const float* bt = &ln_b[i * H2 + c];
    float4 o;
    o.x = (v0 - mu) * rs * g[0] + bt[0];
    o.y = (v1 - mu) * rs * g[1] + bt[1];
    o.z = (v2 - mu) * rs * g[2] + bt[2];
    o.w = (v3 - mu) * rs * g[3] + bt[3];
    *reinterpret_cast<float4*>(&scln[((long)i * ROWS + j) * H2 + c]) = o;
}

// ---------------- K8: final 2-wide projection --------------------------------
__global__ void __launch_bounds__(256) k_w2out(
    const float* __restrict__ h1, const float* __restrict__ W2,
    const float* __restrict__ b2, float* __restrict__ out)
{
    int gw = (blockIdx.x * blockDim.x + threadIdx.x) >> 5;
    int lane = threadIdx.x & 31;
    if (gw >= NA * ROWS) return;
    int i = gw >> 14;
    int j = gw & 16383;
    const float* hr = &h1[((long)i * ROWS + j) * Hh];
    const float* w0 = &W2[(i * 2 + 0) * Hh];
    const float* w1 = &W2[(i * 2 + 1) * Hh];
    float a0 = 0.f, a1 = 0.f;
    #pragma unroll
    for (int q = 0; q < 8; q++) {
        float hv = hr[lane + q * 32];
        a0 = fmaf(hv, w0[lane + q * 32], a0);
        a1 = fmaf(hv, w1[lane + q * 32], a1);
    }
    #pragma unroll
    for (int o = 16; o > 0; o >>= 1) {
        a0 += __shfl_down_sync(0xffffffffu, a0, o);
        a1 += __shfl_down_sync(0xffffffffu, a1, o);
    }
    if (lane == 0) {
        int t = j >> 10, b = j & 1023;
        long base = (((long)i * NDm + t) * Bb_ + b) * 2;
        out[base + 0] = a0 + b2[i * 2 + 0];
        out[base + 1] = a1 + b2[i * 2 + 1];
    }
}

// ---------------- K9: copy final hidden states to output ---------------------
__global__ void __launch_bounds__(256) k_copy_hx(
    const float* __restrict__ h, float* __restrict__ out, int n)
{
    int i = blockIdx.x * blockDim.x + threadIdx.x;
    if (i < n) out[i] = h[i];
}

// ---------------- host orchestration -----------------------------------------
extern "C" void kernel_launch(void* const* d_in, const int* in_sizes, int n_in,
                              void* d_out, int out_size)
{
    const float* plans         = (const float*)d_in[0];
    const float* comm_plans    = (const float*)d_in[1];
    const float* coord_hiddens = (const float*)d_in[2];
    const float* dummy_noise   = (const float*)d_in[3];
    const float* Wi_f = (const float*)d_in[4];
    const float* Wh_f = (const float*)d_in[5];
    const float* Wi_b = (const float*)d_in[6];
    const float* Wh_b = (const float*)d_in[7];
    const float* ln_g = (const float*)d_in[8];
    const float* ln_b = (const float*)d_in[9];
    const float* W1   = (const float*)d_in[10];
    const float* b1   = (const float*)d_in[11];
    const float* W2   = (const float*)d_in[12];
    const float* b2   = (const float*)d_in[13];
    float* out = (float*)d_out;

    float *xg, *gi, *outf, *outb, *scln, *h1, *hst, *hr0, *hr1, *wht;
    int *fwd, *bwd, *scat, *Pm, *Pp, *seq, *emp, *anyc, *anyp;
    unsigned char* mreal;
    cudaGetSymbolAddress((void**)&xg,   g_xg);
    cudaGetSymbolAddress((void**)&gi,   g_gi);
    cudaGetSymbolAddress((void**)&outf, g_outf);
    cudaGetSymbolAddress((void**)&outb, g_outb);
    cudaGetSymbolAddress((void**)&scln, g_scln);
    cudaGetSymbolAddress((void**)&h1,   g_h1);
    cudaGetSymbolAddress((void**)&hst,  g_h);
    cudaGetSymbolAddress((void**)&hr0,  g_hr0);
    cudaGetSymbolAddress((void**)&hr1,  g_hr1);
    cudaGetSymbolAddress((void**)&wht,  g_wht);
    cudaGetSymbolAddress((void**)&fwd,  g_fwd);
    cudaGetSymbolAddress((void**)&bwd,  g_bwd);
    cudaGetSymbolAddress((void**)&scat, g_scat);
    cudaGetSymbolAddress((void**)&Pm,   g_Pmask);
    cudaGetSymbolAddress((void**)&Pp,   g_Ppm);
    cudaGetSymbolAddress((void**)&seq,  g_seq);
    cudaGetSymbolAddress((void**)&emp,  g_empty);
    cudaGetSymbolAddress((void**)&anyc, g_anyc);
    cudaGetSymbolAddress((void**)&anyp, g_anyp);
    cudaGetSymbolAddress((void**)&mreal, g_mreal);

    static int smem_set = 0;
    if (!smem_set) {
        cudaFuncSetAttribute(k_rec_fused,
                             cudaFuncAttributeMaxDynamicSharedMemorySize,
                             RBM * EPISTR * 4);   // 102400 B
        smem_set = 1;
    }

    // masks + packing indices
    k_rowflags<<<1024, 256>>>(comm_plans, plans, anyc, anyp);
    k_maskreal<<<4, 256>>>(anyc, anyp, emp, mreal);
    k_indices<<<1, 1024>>>(mreal, seq, fwd, bwd, scat, Pm, Pp);

    // init hidden states (fp32 + rounded copy) and pre-rounded interleaved Wh
    k_prep_h0<<<(NC * Bb_ * Hh + 255) / 256, 256>>>(coord_hiddens, hst, hr0, NC * Bb_ * Hh);
    k_prep_wh<<<(int)(((long)NC * H3 * Hh + 255) / 256), 256>>>(Wh_f, Wh_b, wht);

    // gather inputs and input projections (interleaved gi layout)
    k_gather<<<dim3(ROWS, NC), 64>>>(plans, comm_plans, dummy_noise, fwd, bwd, emp, xg);
    gemm_tf32<<<dim3(ROWS / BM, H3 / BN, NC), 256>>>(
        xg, Wi_f, Wi_b, gi, nullptr,
        ROWS, H3, TP,
        (long)ROWS * TP, (long)H3 * TP, (long)ROWS * H3, 0, 1, 0, 1);

    // 16 fused recurrent steps
    for (int t = 0; t < NDm; t++) {
        float* hr_in  = (t & 1) ? hr1 : hr0;
        float* hr_nxt = (t & 1) ? hr0 : hr1;
        k_rec_fused<<<dim3(Bb_ / RBM, H3 / RBN, NC), 256, RBM * EPISTR * 4>>>(
            hr_in, hst, hr_nxt, wht, gi, outf, outb, seq, t);
    }

    // scatter + reverse + layernorm
    k_scores_ln<<<dim3(ROWS, NA), 128>>>(outf, outb, scat, seq, ln_g, ln_b, scln);

    // MLP: h1 = relu(scln @ W1^T + b1)
    gemm_tf32<<<dim3(ROWS / BM, Hh / BN, NA), 256>>>(
        scln, W1, W1, h1, b1,
        ROWS, Hh, H2,
        (long)ROWS * H2, (long)Hh * H2, (long)ROWS * Hh, Hh, 0, 1, 0);

    // final projection -> coord_masks (N, ND, B, 2)
    k_w2out<<<(NA * ROWS * 32 + 255) / 256, 256>>>(h1, W2, b2, out);

    // coord_rnn_hxs (N, 2, B, H) appended after coord_masks
    int masks_elems = NA * NDm * Bb_ * 2;
    int hx_elems = NC * Bb_ * Hh;
    if (out_size >= masks_elems + hx_elems) {
        k_copy_hx<<<(hx_elems + 255) / 256, 256>>>(hst, out + masks_elems, hx_elems);
    }
}

// round 9
// speedup vs baseline: 1.3931x; 1.3931x over previous
#include <cuda_runtime.h>
#include <math.h>
#include <stdint.h>

// Problem constants
#define NA   8      // agents
#define NDm  16     // N_DUMMY (timesteps)
#define Bb_  1024   // batch
#define Pp_  128    // plan
#define TP   256    // 2*P
#define Hh   256    // hidden
#define H3   768    // 3*H
#define H2   512    // 2*H
#define NC   16     // chains = agents * 2 dirs
#define ROWS 16384  // NDm * Bb_

// ---------------- scratch (device globals; no allocation allowed) -------------
__device__ float g_xg[NC * ROWS * TP];        // gathered inputs (tf32-rounded)
__device__ float g_gi[(long)NC * ROWS * H3];  // input projections
__device__ float g_gh[NC * Bb_ * H3];         // per-step hidden projections
__device__ float g_outf[NA * ROWS * Hh];      // forward GRU outputs
__device__ float g_outb[NA * ROWS * Hh];      // backward GRU outputs
__device__ float g_scln[NA * ROWS * H2];      // scattered + LN (tf32-rounded)
__device__ float g_h1[NA * ROWS * Hh];        // MLP hidden
__device__ float g_h[NC * Bb_ * Hh];          // GRU hidden state (fp32)
__device__ float g_hr[NC * Bb_ * Hh];         // tf32-rounded shadow of h
__device__ float g_wit[(long)NC * H3 * TP];   // pre-rounded Wi per chain
__device__ float g_wht[NC * H3 * Hh];         // pre-rounded Wh per chain
__device__ float g_w1t[NA * Hh * H2];         // pre-rounded W1
__device__ int   g_fwd[ROWS], g_bwd[ROWS], g_scat[ROWS];
__device__ int   g_Pmask[ROWS], g_Ppm[ROWS];
__device__ int   g_seq[Bb_], g_empty[Bb_];
__device__ int   g_anyc[Bb_ * NA], g_anyp[Bb_ * NA];
__device__ unsigned char g_mreal[NA * Bb_];

__device__ __forceinline__ uint32_t f2tf32(float f) {
    uint32_t u;
    asm("cvt.rna.tf32.f32 %0, %1;" : "=r"(u) : "f"(f));
    return u;
}
__device__ __forceinline__ float roundtf(float f) {
    return __uint_as_float(f2tf32(f));
}

// ---------------- K1: per-(b,n) nonzero row flags ----------------------------
__global__ void __launch_bounds__(256) k_rowflags(
    const float* __restrict__ comm_plans,
    const float* __restrict__ plans,
    int* __restrict__ anyc, int* __restrict__ anyp)
{
    int warp = (blockIdx.x * blockDim.x + threadIdx.x) >> 5;
    int lane = threadIdx.x & 31;
    if (warp >= Bb_ * NA) return;
    float4 c4 = *reinterpret_cast<const float4*>(&comm_plans[(long)warp * Pp_ + lane * 4]);
    bool nzc = (c4.x != 0.f) || (c4.y != 0.f) || (c4.z != 0.f) || (c4.w != 0.f);
    unsigned mc = __ballot_sync(0xffffffffu, nzc);
    float4 p4 = *reinterpret_cast<const float4*>(&plans[(long)warp * Pp_ + lane * 4]);
    bool nzp = (p4.x != 0.f) || (p4.y != 0.f) || (p4.z != 0.f) || (p4.w != 0.f);
    unsigned mp = __ballot_sync(0xffffffffu, nzp);
    if (lane == 0) { anyc[warp] = (mc != 0u); anyp[warp] = (mp != 0u); }
}

// ---------------- K2: empty[b], mask_real[n][b] ------------------------------
__global__ void __launch_bounds__(256) k_maskreal(
    const int* __restrict__ anyc, const int* __restrict__ anyp,
    int* __restrict__ empty, unsigned char* __restrict__ mreal)
{
    int b = blockIdx.x * blockDim.x + threadIdx.x;
    if (b >= Bb_) return;
    int any = 0, ac[NA];
    #pragma unroll
    for (int n = 0; n < NA; n++) { ac[n] = anyc[b * NA + n]; any |= ac[n]; }
    int e = !any;
    empty[b] = e;
    #pragma unroll
    for (int n = 0; n < NA; n++)
        mreal[n * Bb_ + b] = e ? (unsigned char)anyp[b * NA + n] : (unsigned char)ac[n];
}

// ---------------- K3: packing index maps (single block) ----------------------
__global__ void __launch_bounds__(1024) k_indices(
    const unsigned char* __restrict__ mreal,
    int* __restrict__ seq_len,
    int* __restrict__ fwd_src, int* __restrict__ bwd_src,
    int* __restrict__ scat_src,
    int* __restrict__ Pmask, int* __restrict__ Ppm)
{
    int tid = threadIdx.x;            // 1024 threads
    {
        int b = tid, s = NDm - NA;
        #pragma unroll
        for (int t = 0; t < NA; t++) s += mreal[t * Bb_ + b];
        seq_len[b] = s;
    }
    __syncthreads();

    int base_j = tid * 16;
    unsigned m_bits = 0, p_bits = 0;
    int cm = 0, cp = 0;
    for (int r = 0; r < 16; r++) {
        int j = base_j + r;
        int t = j >> 10, b = j & 1023;
        int m = (t < NA) ? (int)mreal[j] : 1;
        int p = (t < seq_len[b]) ? 1 : 0;
        if (m) { m_bits |= 1u << r; cm++; }
        if (p) { p_bits |= 1u << r; cp++; }
    }
    __shared__ int wm[32], wp[32], tot;
    int lane = tid & 31, wid = tid >> 5;
    int sm = cm, sp = cp;
    #pragma unroll
    for (int o = 1; o < 32; o <<= 1) {
        int v = __shfl_up_sync(0xffffffffu, sm, o); if (lane >= o) sm += v;
        v     = __shfl_up_sync(0xffffffffu, sp, o); if (lane >= o) sp += v;
    }
    if (lane == 31) { wm[wid] = sm; wp[wid] = sp; }
    __syncthreads();
    if (wid == 0) {
        int a = wm[lane], c = wp[lane];
        #pragma unroll
        for (int o = 1; o < 32; o <<= 1) {
            int v = __shfl_up_sync(0xffffffffu, a, o); if (lane >= o) a += v;
            v     = __shfl_up_sync(0xffffffffu, c, o); if (lane >= o) c += v;
        }
        wm[lane] = a; wp[lane] = c;
        if (lane == 31) tot = a;
    }
    __syncthreads();
    int basem = sm - cm + (wid ? wm[wid - 1] : 0);
    int basep = sp - cp + (wid ? wp[wid - 1] : 0);
    int Ktot = tot;

    int km = basem, kp = basep;
    for (int r = 0; r < 16; r++) {
        int j = base_j + r;
        fwd_src[j] = -1;
        if (m_bits & (1u << r)) { Pmask[km] = j; scat_src[j] = km; km++; }
        else scat_src[j] = -1;
        if (p_bits & (1u << r)) { Ppm[kp] = j; kp++; }
    }
    __syncthreads();
    for (int k = tid; k < Ktot; k += 1024) fwd_src[Ppm[k]] = Pmask[k];
    __syncthreads();
    for (int r = 0; r < 16; r++) {
        int j = base_j + r;
        int t = j >> 10, b = j & 1023;
        int sl = seq_len[b];
        bwd_src[j] = (t < sl) ? fwd_src[(sl - 1 - t) * Bb_ + b] : -1;
    }
}

// ---------------- K4: init h (fp32 + tf32-rounded copy) ----------------------
__global__ void __launch_bounds__(256) k_prep_h0(
    const float* __restrict__ src, float* __restrict__ h, float* __restrict__ hr, int n)
{
    int i = blockIdx.x * blockDim.x + threadIdx.x;
    if (i < n) {
        float v = src[i];
        h[i] = v;
        hr[i] = roundtf(v);
    }
}

// ---------------- K4b/c/d: pre-round weights ---------------------------------
__global__ void __launch_bounds__(256) k_prep_wi(
    const float* __restrict__ Wi_f, const float* __restrict__ Wi_b,
    float* __restrict__ wit)
{
    long idx = (long)blockIdx.x * 256 + threadIdx.x;
    if (idx >= (long)NC * H3 * TP) return;
    int k = (int)(idx % TP);
    long r2 = idx / TP;
    int n = (int)(r2 % H3);
    int z = (int)(r2 / H3);
    int i = z >> 1, d = z & 1;
    const float* src = d ? Wi_b : Wi_f;
    wit[idx] = roundtf(src[((long)i * H3 + n) * TP + k]);
}

__global__ void __launch_bounds__(256) k_prep_wh(
    const float* __restrict__ Wh_f, const float* __restrict__ Wh_b,
    float* __restrict__ wht)
{
    long idx = (long)blockIdx.x * 256 + threadIdx.x;
    if (idx >= (long)NC * H3 * Hh) return;
    int k = (int)(idx % Hh);
    long r2 = idx / Hh;
    int n = (int)(r2 % H3);
    int z = (int)(r2 / H3);
    int i = z >> 1, d = z & 1;
    const float* src = d ? Wh_b : Wh_f;
    wht[idx] = roundtf(src[((long)i * H3 + n) * Hh + k]);
}

__global__ void __launch_bounds__(256) k_prep_w1(
    const float* __restrict__ W1, float* __restrict__ w1t)
{
    long idx = (long)blockIdx.x * 256 + threadIdx.x;
    if (idx >= (long)NA * Hh * H2) return;
    w1t[idx] = roundtf(W1[idx]);
}

// ---------------- K5: gather x rows per chain (writes tf32-rounded) ----------
__global__ void __launch_bounds__(64) k_gather(
    const float* __restrict__ plans, const float* __restrict__ comm_plans,
    const float* __restrict__ dummy,
    const int* __restrict__ fwd_src, const int* __restrict__ bwd_src,
    const int* __restrict__ empty, float* __restrict__ xg)
{
    int j = blockIdx.x;           // 0..16383 packed row (t*B+b)
    int z = blockIdx.y;           // chain
    int c = threadIdx.x * 4;      // 64 threads * 4 = 256 feats
    int i = z >> 1, d = z & 1;
    int src = (d ? bwd_src : fwd_src)[j];
    float4 v = make_float4(0.f, 0.f, 0.f, 0.f);
    if (src >= 0) {
        int ts = src >> 10, bs = src & 1023;
        if (ts < NA) {
            if (c < Pp_) {
                v = *reinterpret_cast<const float4*>(&plans[((long)bs * NA + i) * Pp_ + c]);
            } else {
                const float* sp = empty[bs] ? plans : comm_plans;
                v = *reinterpret_cast<const float4*>(&sp[((long)bs * NA + ts) * Pp_ + (c - Pp_)]);
            }
        } else {
            v = *reinterpret_cast<const float4*>(
                &dummy[(((long)i * (NDm - NA) + (ts - NA)) * Bb_ + bs) * TP + c]);
        }
    }
    v.x = roundtf(v.x); v.y = roundtf(v.y); v.z = roundtf(v.z); v.w = roundtf(v.w);
    *reinterpret_cast<float4*>(&xg[((long)z * ROWS + j) * TP + c]) = v;
}

// ---------------- tf32 tensor-core NT GEMM, pre-rounded operands -------------
// C[m,n] = sum_k A[m,k]*W[n,k] (+bias,+relu). BM=BN=128, BK=16.
// 3-stage cp.async pipeline, one __syncthreads per K-step.
#define BM 128
#define BN 128
#define BKq 16
#define SSTR 20
#define GSTG_W ((BM + BN) * SSTR)   // 5120 words per stage
#define GSMEM_BYTES (3 * GSTG_W * 4)  // 61440

__device__ __forceinline__ void cpa16(uint32_t dst, const float* src) {
    asm volatile("cp.async.ca.shared.global [%0], [%1], 16;" :: "r"(dst), "l"(src));
}

__global__ void __launch_bounds__(256, 2) gemm_pre(
    const float* __restrict__ Abase, const float* __restrict__ Wbase,
    float* __restrict__ Cbase, const float* __restrict__ biasBase,
    int M, int N, int K,
    long sA, long sB, long sC, long sBias, int relu)
{
    extern __shared__ float dynsm[];
    int z = blockIdx.z;
    const float* A = Abase + (long)z * sA;
    const float* W = Wbase + (long)z * sB;
    float* C = Cbase + (long)z * sC;
    const float* bias = biasBase ? (biasBase + (long)z * sBias) : nullptr;

    int tid  = threadIdx.x;
    int lane = tid & 31;
    int warp = tid >> 5;
    int wm   = warp & 3;
    int wn   = warp >> 2;
    int m0   = blockIdx.x * BM;
    int n0   = blockIdx.y * BN;

    uint32_t smem_base = (uint32_t)__cvta_generic_to_shared((void*)dynsm);

    float acc[2][8][4];
    #pragma unroll
    for (int a = 0; a < 2; a++)
        #pragma unroll
        for (int b = 0; b < 8; b++)
            #pragma unroll
            for (int c = 0; c < 4; c++) acc[a][b][c] = 0.f;

    int lrow = tid >> 2;
    int lkq  = (tid & 3) * 4;

    auto load_stage = [&](int buf, int k0) {
        uint32_t sAa = smem_base + (buf * GSTG_W) * 4;
        uint32_t sBb = smem_base + (buf * GSTG_W + BM * SSTR) * 4;
        #pragma unroll
        for (int p = 0; p < 2; p++) {
            int row = lrow + p * 64;
            cpa16(sAa + (row * SSTR + lkq) * 4, &A[(long)(m0 + row) * K + k0 + lkq]);
            cpa16(sBb + (row * SSTR + lkq) * 4, &W[(long)(n0 + row) * K + k0 + lkq]);
        }
    };

    const int NSTG = K / BKq;
    load_stage(0, 0);
    asm volatile("cp.async.commit_group;");
    load_stage(1, BKq);
    asm volatile("cp.async.commit_group;");

    for (int s = 0; s < NSTG; s++) {
        if (s + 1 < NSTG) asm volatile("cp.async.wait_group 1;");
        else              asm volatile("cp.async.wait_group 0;");
        __syncthreads();
        if (s + 2 < NSTG) {
            load_stage((s + 2) % 3, (s + 2) * BKq);
            asm volatile("cp.async.commit_group;");
        }
        const uint32_t* Ash = reinterpret_cast<const uint32_t*>(dynsm + (s % 3) * GSTG_W);
        const uint32_t* Bsh = Ash + BM * SSTR;

        #pragma unroll
        for (int ks = 0; ks < BKq; ks += 8) {
            uint32_t afr[2][4], bfr[8][2];
            int ar = wm * 32 + (lane >> 2);
            int ac = ks + (lane & 3);
            #pragma unroll
            for (int mt = 0; mt < 2; mt++) {
                int r = ar + mt * 16;
                afr[mt][0] = Ash[r * SSTR + ac];
                afr[mt][1] = Ash[(r + 8) * SSTR + ac];
                afr[mt][2] = Ash[r * SSTR + ac + 4];
                afr[mt][3] = Ash[(r + 8) * SSTR + ac + 4];
            }
            int bn = wn * 64 + (lane >> 2);
            int bk = ks + (lane & 3);
            #pragma unroll
            for (int nt = 0; nt < 8; nt++) {
                int n = bn + nt * 8;
                bfr[nt][0] = Bsh[n * SSTR + bk];
                bfr[nt][1] = Bsh[n * SSTR + bk + 4];
            }
            #pragma unroll
            for (int mt = 0; mt < 2; mt++)
                #pragma unroll
                for (int nt = 0; nt < 8; nt++)
                    asm volatile(
                        "mma.sync.aligned.m16n8k8.row.col.f32.tf32.tf32.f32 "
                        "{%0,%1,%2,%3}, {%4,%5,%6,%7}, {%8,%9}, {%0,%1,%2,%3};"
                        : "+f"(acc[mt][nt][0]), "+f"(acc[mt][nt][1]),
                          "+f"(acc[mt][nt][2]), "+f"(acc[mt][nt][3])
                        : "r"(afr[mt][0]), "r"(afr[mt][1]), "r"(afr[mt][2]), "r"(afr[mt][3]),
                          "r"(bfr[nt][0]), "r"(bfr[nt][1]));
        }
    }

    #pragma unroll
    for (int mt = 0; mt < 2; mt++) {
        int r0 = m0 + wm * 32 + mt * 16 + (lane >> 2);
        #pragma unroll
        for (int nt = 0; nt < 8; nt++) {
            int cb = n0 + wn * 64 + nt * 8 + (lane & 3) * 2;
            float v0 = acc[mt][nt][0], v1 = acc[mt][nt][1];
            float v2 = acc[mt][nt][2], v3 = acc[mt][nt][3];
            if (bias) {
                float b0v = bias[cb], b1v = bias[cb + 1];
                v0 += b0v; v1 += b1v; v2 += b0v; v3 += b1v;
            }
            if (relu) {
                v0 = fmaxf(v0, 0.f); v1 = fmaxf(v1, 0.f);
                v2 = fmaxf(v2, 0.f); v3 = fmaxf(v3, 0.f);
            }
            *reinterpret_cast<float2*>(&C[(long)r0 * N + cb])       = make_float2(v0, v1);
            *reinterpret_cast<float2*>(&C[(long)(r0 + 8) * N + cb]) = make_float2(v2, v3);
        }
    }
}

// ---------------- K6: GRU gates + state update (also writes rounded h) -------
__global__ void __launch_bounds__(256) k_gates(
    const float* __restrict__ gi, const float* __restrict__ gh,
    float* __restrict__ h, float* __restrict__ hr,
    float* __restrict__ outf, float* __restrict__ outb,
    const int* __restrict__ seq_len, int t)
{
    int b = blockIdx.x;          // batch
    int z = blockIdx.y;          // chain
    int hc = threadIdx.x;        // hidden col (256)
    int i = z >> 1, d = z & 1;
    long gio = ((long)z * ROWS + t * Bb_ + b) * H3 + hc;
    long gho = ((long)z * Bb_ + b) * H3 + hc;
    long ho  = ((long)z * Bb_ + b) * Hh + hc;
    float gir = gi[gio], giz = gi[gio + Hh], gin = gi[gio + 2 * Hh];
    float ghr = gh[gho], ghz = gh[gho + Hh], ghn = gh[gho + 2 * Hh];
    float hp = h[ho];
    float r  = 1.f / (1.f + expf(-(gir + ghr)));
    float zz = 1.f / (1.f + expf(-(giz + ghz)));
    float nn = tanhf(gin + r * ghn);
    float hn = (1.f - zz) * nn + zz * hp;
    bool v = t < seq_len[b];
    float hnew = v ? hn : hp;
    h[ho] = hnew;
    hr[ho] = roundtf(hnew);
    float* op = (d == 0 ? outf : outb) + ((long)i * ROWS + t * Bb_ + b) * Hh + hc;
    *op = v ? hn : 0.f;
}

// ---------------- K7: scatter + reverse + layernorm (writes rounded) ---------
__global__ void __launch_bounds__(128) k_scores_ln(
    const float* __restrict__ outf, const float* __restrict__ outb,
    const int* __restrict__ scat, const int* __restrict__ seq_len,
    const float* __restrict__ ln_g, const float* __restrict__ ln_b,
    float* __restrict__ scln)
{
    int j = blockIdx.x;          // row (t*B+b) in mask layout
    int i = blockIdx.y;          // agent
    int tid = threadIdx.x;       // 128 threads, 4 cols each
    __shared__ float s1[128], s2[128];
    float v0 = 0.f, v1 = 0.f, v2 = 0.f, v3 = 0.f;
    int k = scat[j];
    if (k >= 0) {
        int tp = k >> 10, bp = k & 1023;
        if (tid < 64) {
            float4 f = *reinterpret_cast<const float4*>(&outf[((long)i * ROWS + k) * Hh + tid * 4]);
            v0 = f.x; v1 = f.y; v2 = f.z; v3 = f.w;
        } else {
            int sl = seq_len[bp];
            if (tp < sl) {
                int rb = sl - 1 - tp;
                float4 f = *reinterpret_cast<const float4*>(
                    &outb[((long)i * ROWS + rb * Bb_ + bp) * Hh + (tid - 64) * 4]);
                v0 = f.x; v1 = f.y; v2 = f.z; v3 = f.w;
            }
        }
    }
    s1[tid] = v0 + v1 + v2 + v3;
    s2[tid] = v0 * v0 + v1 * v1 + v2 * v2 + v3 * v3;
    __syncthreads();
    for (int off = 64; off > 0; off >>= 1) {
        if (tid < off) { s1[tid] += s1[tid + off]; s2[tid] += s2[tid + off]; }
        __syncthreads();
    }
    float mu  = s1[0] * (1.f / H2);
    float var = s2[0] * (1.f / H2) - mu * mu;
    float rs  = rsqrtf(var + 1e-5f);
    int c = tid * 4;
    const float* g = &ln_g[i * H2 + c];
    const float* bt = &ln_b[i * H2 + c];
    float4 o;
    o.x = roundtf((v0 - mu) * rs * g[0] + bt[0]);
    o.y = roundtf((v1 - mu) * rs * g[1] + bt[1]);
    o.z = roundtf((v2 - mu) * rs * g[2] + bt[2]);
    o.w = roundtf((v3 - mu) * rs * g[3] + bt[3]);
    *reinterpret_cast<float4*>(&scln[((long)i * ROWS + j) * H2 + c]) = o;
}

// ---------------- K8: final 2-wide projection --------------------------------
__global__ void __launch_bounds__(256) k_w2out(
    const float* __restrict__ h1, const float* __restrict__ W2,
    const float* __restrict__ b2, float* __restrict__ out)
{
    int gw = (blockIdx.x * blockDim.x + threadIdx.x) >> 5;
    int lane = threadIdx.x & 31;
    if (gw >= NA * ROWS) return;
    int i = gw >> 14;
    int j = gw & 16383;
    const float* hr = &h1[((long)i * ROWS + j) * Hh];
    const float* w0 = &W2[(i * 2 + 0) * Hh];
    const float* w1 = &W2[(i * 2 + 1) * Hh];
    float a0 = 0.f, a1 = 0.f;
    #pragma unroll
    for (int q = 0; q < 8; q++) {
        float hv = hr[lane + q * 32];
        a0 = fmaf(hv, w0[lane + q * 32], a0);
        a1 = fmaf(hv, w1[lane + q * 32], a1);
    }
    #pragma unroll
    for (int o = 16; o > 0; o >>= 1) {
        a0 += __shfl_down_sync(0xffffffffu, a0, o);
        a1 += __shfl_down_sync(0xffffffffu, a1, o);
    }
    if (lane == 0) {
        int t = j >> 10, b = j & 1023;
        long base = (((long)i * NDm + t) * Bb_ + b) * 2;
        out[base + 0] = a0 + b2[i * 2 + 0];
        out[base + 1] = a1 + b2[i * 2 + 1];
    }
}

// ---------------- K9: copy final hidden states to output ---------------------
__global__ void __launch_bounds__(256) k_copy_hx(
    const float* __restrict__ h, float* __restrict__ out, int n)
{
    int i = blockIdx.x * blockDim.x + threadIdx.x;
    if (i < n) out[i] = h[i];
}

// ---------------- host orchestration -----------------------------------------
extern "C" void kernel_launch(void* const* d_in, const int* in_sizes, int n_in,
                              void* d_out, int out_size)
{
    const float* plans         = (const float*)d_in[0];
    const float* comm_plans    = (const float*)d_in[1];
    const float* coord_hiddens = (const float*)d_in[2];
    const float* dummy_noise   = (const float*)d_in[3];
    const float* Wi_f = (const float*)d_in[4];
    const float* Wh_f = (const float*)d_in[5];
    const float* Wi_b = (const float*)d_in[6];
    const float* Wh_b = (const float*)d_in[7];
    const float* ln_g = (const float*)d_in[8];
    const float* ln_b = (const float*)d_in[9];
    const float* W1   = (const float*)d_in[10];
    const float* b1   = (const float*)d_in[11];
    const float* W2   = (const float*)d_in[12];
    const float* b2   = (const float*)d_in[13];
    float* out = (float*)d_out;

    float *xg, *gi, *gh, *outf, *outb, *scln, *h1, *hst, *hr, *wit, *wht, *w1t;
    int *fwd, *bwd, *scat, *Pm, *Pp, *seq, *emp, *anyc, *anyp;
    unsigned char* mreal;
    cudaGetSymbolAddress((void**)&xg,   g_xg);
    cudaGetSymbolAddress((void**)&gi,   g_gi);
    cudaGetSymbolAddress((void**)&gh,   g_gh);
    cudaGetSymbolAddress((void**)&outf, g_outf);
    cudaGetSymbolAddress((void**)&outb, g_outb);
    cudaGetSymbolAddress((void**)&scln, g_scln);
    cudaGetSymbolAddress((void**)&h1,   g_h1);
    cudaGetSymbolAddress((void**)&hst,  g_h);
    cudaGetSymbolAddress((void**)&hr,   g_hr);
    cudaGetSymbolAddress((void**)&wit,  g_wit);
    cudaGetSymbolAddress((void**)&wht,  g_wht);
    cudaGetSymbolAddress((void**)&w1t,  g_w1t);
    cudaGetSymbolAddress((void**)&fwd,  g_fwd);
    cudaGetSymbolAddress((void**)&bwd,  g_bwd);
    cudaGetSymbolAddress((void**)&scat, g_scat);
    cudaGetSymbolAddress((void**)&Pm,   g_Pmask);
    cudaGetSymbolAddress((void**)&Pp,   g_Ppm);
    cudaGetSymbolAddress((void**)&seq,  g_seq);
    cudaGetSymbolAddress((void**)&emp,  g_empty);
    cudaGetSymbolAddress((void**)&anyc, g_anyc);
    cudaGetSymbolAddress((void**)&anyp, g_anyp);
    cudaGetSymbolAddress((void**)&mreal, g_mreal);

    cudaFuncSetAttribute(gemm_pre, cudaFuncAttributeMaxDynamicSharedMemorySize,
                         GSMEM_BYTES);

    // masks + packing indices
    k_rowflags<<<1024, 256>>>(comm_plans, plans, anyc, anyp);
    k_maskreal<<<4, 256>>>(anyc, anyp, emp, mreal);
    k_indices<<<1, 1024>>>(mreal, seq, fwd, bwd, scat, Pm, Pp);

    // init hidden + pre-round weights
    k_prep_h0<<<(NC * Bb_ * Hh + 255) / 256, 256>>>(coord_hiddens, hst, hr, NC * Bb_ * Hh);
    k_prep_wi<<<(int)(((long)NC * H3 * TP + 255) / 256), 256>>>(Wi_f, Wi_b, wit);
    k_prep_wh<<<(int)(((long)NC * H3 * Hh + 255) / 256), 256>>>(Wh_f, Wh_b, wht);
    k_prep_w1<<<(int)(((long)NA * Hh * H2 + 255) / 256), 256>>>(W1, w1t);

    // gather inputs (rounded) and input projections
    k_gather<<<dim3(ROWS, NC), 64>>>(plans, comm_plans, dummy_noise, fwd, bwd, emp, xg);
    gemm_pre<<<dim3(ROWS / BM, H3 / BN, NC), 256, GSMEM_BYTES>>>(
        xg, wit, gi, nullptr,
        ROWS, H3, TP,
        (long)ROWS * TP, (long)H3 * TP, (long)ROWS * H3, 0, 0);

    // 16 recurrent steps: gh GEMM + gates
    for (int t = 0; t < NDm; t++) {
        gemm_pre<<<dim3(Bb_ / BM, H3 / BN, NC), 256, GSMEM_BYTES>>>(
            hr, wht, gh, nullptr,
            Bb_, H3, Hh,
            (long)Bb_ * Hh, (long)H3 * Hh, (long)Bb_ * H3, 0, 0);
        k_gates<<<dim3(Bb_, NC), Hh>>>(gi, gh, hst, hr, outf, outb, seq, t);
    }

    // scatter + reverse + layernorm (rounded output)
    k_scores_ln<<<dim3(ROWS, NA), 128>>>(outf, outb, scat, seq, ln_g, ln_b, scln);

    // MLP: h1 = relu(scln @ W1^T + b1)   — relu flag = 1 (R8 bug fix)
    gemm_pre<<<dim3(ROWS / BM, Hh / BN, NA), 256, GSMEM_BYTES>>>(
        scln, w1t, h1, b1,
        ROWS, Hh, H2,
        (long)ROWS * H2, (long)Hh * H2, (long)ROWS * Hh, Hh, 1);

    // final projection -> coord_masks (N, ND, B, 2)
    k_w2out<<<(NA * ROWS * 32 + 255) / 256, 256>>>(h1, W2, b2, out);

    // coord_rnn_hxs (N, 2, B, H) appended after coord_masks
    int masks_elems = NA * NDm * Bb_ * 2;
    int hx_elems = NC * Bb_ * Hh;
    if (out_size >= masks_elems + hx_elems) {
        k_copy_hx<<<(hx_elems + 255) / 256, 256>>>(hst, out + masks_elems, hx_elems);
    }
}